// round 5
// baseline (speedup 1.0000x reference)
#include <cuda_runtime.h>
#include <cstdint>
#include <cstddef>

#define NPTS 500000
#define NVOX 65536

// ---------------- scratch (device globals; no allocations allowed) ----------
__device__ float g_pf2 [(size_t)NPTS * 128];   // 256 MB  relu(point MLP2)
__device__ float g_vox1[(size_t)NVOX * 128];   //  32 MB  segment-max #1 (init 0)
__device__ float g_g3  [(size_t)NVOX * 256];   //  64 MB  voxf @ W3_top + b3
__device__ float g_vox2[(size_t)NVOX * 256];   //  64 MB  segment-max #2 (init 0)
__device__ int   g_idx_is64;

// ---------------- idx dtype probe (int64 vs int32 delivery) -----------------
__global__ void kdetect(const unsigned* __restrict__ raw) {
    // int64 voxel ids < 65536 -> every hi word is 0; int32 data -> sampled
    // words are random voxel ids, essentially never all zero.
    unsigned w = raw[threadIdx.x * 2 + 1];               // first 2KB only (safe)
    unsigned any = __ballot_sync(0xffffffffu, w != 0u);
    __shared__ int s[8];
    if ((threadIdx.x & 31) == 0) s[threadIdx.x >> 5] = (any != 0u);
    __syncthreads();
    if (threadIdx.x == 0) {
        int t = 0;
        #pragma unroll
        for (int i = 0; i < 8; i++) t |= s[i];
        g_idx_is64 = !t;
    }
}

__device__ __forceinline__ int load_idx(const void* idxp, long long row, int is64) {
    return is64 ? (int)((const long long*)idxp)[row] : ((const int*)idxp)[row];
}

// ---------------- K1: inp -> pf1 -> pf2 (store) + scatter-max vox1 ----------
// smem floats: W1s 384 | b1s 64 | W2s 8192 | b2s 128
#define K1_SMEM_FLOATS (384 + 64 + 8192 + 128)

__global__ void k1(const float* __restrict__ inp, const void* __restrict__ idxp,
                   const float* __restrict__ W1, const float* __restrict__ b1,
                   const float* __restrict__ W2, const float* __restrict__ b2) {
    extern __shared__ float sm[];
    float* W1s = sm;                 // 6*64
    float* b1s = W1s + 384;          // 64
    float* W2s = b1s + 64;           // 64*128
    float* b2s = W2s + 8192;         // 128
    int tid = threadIdx.x;

    for (int i = tid; i < 384; i += 256) W1s[i] = W1[i];
    if (tid < 64)  b1s[tid] = b1[tid];
    for (int i = tid; i < 8192; i += 256) W2s[i] = W2[i];
    if (tid < 128) b2s[tid] = b2[tid];
    __syncthreads();

    long long p = (long long)blockIdx.x * 256 + tid;
    if (p >= NPTS) return;
    const int is64 = g_idx_is64;

    float x[6];
    #pragma unroll
    for (int c = 0; c < 6; c++) x[c] = inp[p * 6 + c];

    // pf1 = relu(x @ W1 + b1), register-resident
    float pf1[64];
    #pragma unroll
    for (int j = 0; j < 64; j++) {
        float a = b1s[j];
        #pragma unroll
        for (int c = 0; c < 6; c++) a = fmaf(x[c], W1s[c * 64 + j], a);
        pf1[j] = fmaxf(a, 0.f);
    }

    long long vox = load_idx(idxp, p, is64);
    float* dst = g_pf2 + (size_t)p * 128;
    float* vdst = g_vox1 + (size_t)vox * 128;

    #pragma unroll
    for (int cj = 0; cj < 4; cj++) {
        float acc[32];
        #pragma unroll
        for (int j = 0; j < 32; j++) acc[j] = b2s[cj * 32 + j];
        #pragma unroll
        for (int k = 0; k < 64; k++) {
            float pv = pf1[k];
            const float* wr = &W2s[k * 128 + cj * 32];
            #pragma unroll
            for (int j = 0; j < 32; j++) acc[j] = fmaf(pv, wr[j], acc[j]);
        }
        #pragma unroll
        for (int j = 0; j < 32; j++) acc[j] = fmaxf(acc[j], 0.f);
        // vectorized pf2 store (16B aligned: dst row is 512B aligned)
        #pragma unroll
        for (int j4 = 0; j4 < 8; j4++)
            *(float4*)&dst[cj * 32 + j4 * 4] =
                make_float4(acc[j4*4+0], acc[j4*4+1], acc[j4*4+2], acc[j4*4+3]);
        #pragma unroll
        for (int j = 0; j < 32; j++) {
            float v = acc[j];
            if (v > vdst[cj * 32 + j])
                atomicMax((int*)&vdst[cj * 32 + j], __float_as_int(v));
        }
    }
}

// ---------------- shared GEMM helpers (256 threads, 64-row tiles) -----------
// 8x8 microtile over N=256: thread owns cols {cx..cx+3, 128+cx..128+cx+3}
// A loads vectorized: float4 per row (r0 uniform per warp -> broadcast
// LDS.128; cx spans warp -> conflict-free B LDS.128).
__device__ __forceinline__ void mma16_8x8(const float* __restrict__ A, int lda, int ks,
                                          const float* __restrict__ Ws,
                                          int r0, int cx, float (&acc)[8][8]) {
    #pragma unroll
    for (int k4 = 0; k4 < 4; k4++) {
        float4 a4[8];
        #pragma unroll
        for (int i = 0; i < 8; i++)
            a4[i] = *(const float4*)&A[(r0 + i) * lda + ks + k4 * 4];
        #pragma unroll
        for (int kk = 0; kk < 4; kk++) {
            float4 bA = *(const float4*)&Ws[(k4 * 4 + kk) * 256 + cx];
            float4 bB = *(const float4*)&Ws[(k4 * 4 + kk) * 256 + 128 + cx];
            float b[8] = {bA.x, bA.y, bA.z, bA.w, bB.x, bB.y, bB.z, bB.w};
            #pragma unroll
            for (int i = 0; i < 8; i++) {
                float av = (kk == 0) ? a4[i].x : (kk == 1) ? a4[i].y
                         : (kk == 2) ? a4[i].z : a4[i].w;
                #pragma unroll
                for (int j = 0; j < 8; j++) acc[i][j] = fmaf(av, b[j], acc[i][j]);
            }
        }
    }
}

__device__ __forceinline__ int col_of(int cx, int j) {
    return (j < 4) ? (cx + j) : (128 + cx + (j - 4));
}

// Prefetch one 16x256 weight tile into registers / store to smem buffer.
__device__ __forceinline__ void ldg_w256(float (&r)[16], const float* __restrict__ W,
                                         int ks, int tid) {
    #pragma unroll
    for (int t = 0; t < 16; t++) {
        int i = tid + t * 256;
        r[t] = W[(size_t)(ks + (i >> 8)) * 256 + (i & 255)];
    }
}
__device__ __forceinline__ void sts_w256(float* Ws, const float (&r)[16], int tid) {
    #pragma unroll
    for (int t = 0; t < 16; t++) Ws[tid + t * 256] = r[t];
}

// Double-buffered K-loop: one __syncthreads per tile, LDG overlapped with FMA.
// Ws must hold 2*4096 floats. KTOT in {128, 256}.
__device__ __forceinline__ void gemm_dbuf(const float* __restrict__ A, int lda,
                                          const float* __restrict__ W, int KTOT,
                                          float* Ws, int r0, int cx, int tid,
                                          float (&acc)[8][8]) {
    const int T = KTOT / 16;
    float wreg[16];
    ldg_w256(wreg, W, 0, tid);
    sts_w256(Ws, wreg, tid);
    __syncthreads();
    for (int t = 0; t < T; t++) {
        float* cur  = Ws + (t & 1) * 4096;
        float* next = Ws + ((t + 1) & 1) * 4096;
        if (t + 1 < T) ldg_w256(wreg, W, (t + 1) * 16, tid);
        mma16_8x8(A, lda, t * 16, cur, r0, cx, acc);
        if (t + 1 < T) {
            sts_w256(next, wreg, tid);
            __syncthreads();
        }
    }
}

// ---------------- K2: vox1 -> voxf(relu,Wv1,bv1) -> g3 = voxf@W3top + b3 ----
// smem floats: As 64*128 | Bs 64*128 | Ws 2*4096 | bias 256
#define K2_SMEM_FLOATS (8192 + 8192 + 8192 + 256)

__global__ void k2(const float* __restrict__ Wv1, const float* __restrict__ bv1,
                   const float* __restrict__ W3, const float* __restrict__ b3) {
    extern __shared__ float sm[];
    float* As = sm;               // [64][128]
    float* Bs = As + 8192;        // [64][128]
    float* Ws = Bs + 8192;        // 2*[16][256] (phase1 uses first [16][128])
    float* bias = Ws + 8192;      // 256
    int tid = threadIdx.x;
    int vb = blockIdx.x * 64;

    for (int i = tid * 4; i < 8192; i += 1024)
        *(float4*)&As[i] = *(const float4*)&g_vox1[(size_t)vb * 128 + i];
    if (tid < 128) bias[tid] = bv1[tid];
    __syncthreads();

    // Phase 1: Bs = relu(As @ Wv1 + bv1)  M=64 N=128 K=128
    {
        int cx = (tid & 15) * 4;          // cols {cx..cx+3, 64+cx..}
        int r0 = (tid >> 4) * 4;
        float acc[4][8];
        #pragma unroll
        for (int i = 0; i < 4; i++)
            #pragma unroll
            for (int j = 0; j < 8; j++) acc[i][j] = 0.f;

        for (int ks = 0; ks < 128; ks += 16) {
            for (int i = tid; i < 2048; i += 256)
                Ws[i] = Wv1[(size_t)(ks + (i >> 7)) * 128 + (i & 127)];
            __syncthreads();
            #pragma unroll
            for (int k4 = 0; k4 < 4; k4++) {
                float4 a4[4];
                #pragma unroll
                for (int i = 0; i < 4; i++)
                    a4[i] = *(const float4*)&As[(r0 + i) * 128 + ks + k4 * 4];
                #pragma unroll
                for (int kk = 0; kk < 4; kk++) {
                    float4 bA = *(const float4*)&Ws[(k4 * 4 + kk) * 128 + cx];
                    float4 bB = *(const float4*)&Ws[(k4 * 4 + kk) * 128 + 64 + cx];
                    float b[8] = {bA.x, bA.y, bA.z, bA.w, bB.x, bB.y, bB.z, bB.w};
                    #pragma unroll
                    for (int i = 0; i < 4; i++) {
                        float av = (kk == 0) ? a4[i].x : (kk == 1) ? a4[i].y
                                 : (kk == 2) ? a4[i].z : a4[i].w;
                        #pragma unroll
                        for (int j = 0; j < 8; j++)
                            acc[i][j] = fmaf(av, b[j], acc[i][j]);
                    }
                }
            }
            __syncthreads();
        }
        #pragma unroll
        for (int i = 0; i < 4; i++)
            #pragma unroll
            for (int j = 0; j < 8; j++) {
                int col = (j < 4) ? (cx + j) : (64 + cx + (j - 4));
                Bs[(r0 + i) * 128 + col] = fmaxf(acc[i][j] + bias[col], 0.f);
            }
    }
    __syncthreads();
    bias[tid] = b3[tid];   // published by gemm_dbuf's first __syncthreads

    // Phase 2: g3 = Bs @ W3[0:128,:] + b3   M=64 N=256 K=128 (no relu)
    {
        int cx = (tid & 31) * 4;
        int r0 = (tid >> 5) * 8;
        float acc[8][8];
        #pragma unroll
        for (int i = 0; i < 8; i++)
            #pragma unroll
            for (int j = 0; j < 8; j++) acc[i][j] = 0.f;

        gemm_dbuf(Bs, 128, W3, 128, Ws, r0, cx, tid, acc);

        #pragma unroll
        for (int i = 0; i < 8; i++) {
            float* out = g_g3 + (size_t)(vb + r0 + i) * 256;
            #pragma unroll
            for (int j = 0; j < 8; j++) {
                int col = col_of(cx, j);
                out[col] = acc[i][j] + bias[col];
            }
        }
    }
}

// ---------------- K3: pf2 -> (@W3bot + g3[idx], relu) -> (@W4+b4, relu) -> max
// smem floats: As 64*128 | Bs 64*256 | Ws 2*4096 | bias 256 | idxs 64 ints
#define K3_SMEM_BYTES ((8192 + 16384 + 8192 + 256) * 4 + 64 * 4)

__global__ void k3(const void* __restrict__ idxp,
                   const float* __restrict__ W3, const float* __restrict__ W4,
                   const float* __restrict__ b4) {
    extern __shared__ float sm[];
    float* As = sm;                // [64][128] pf2 tile
    float* Bs = As + 8192;         // [64][256] pf4 tile
    float* Ws = Bs + 16384;        // 2*[16][256]
    float* bias = Ws + 8192;       // 256 (b4)
    int* idxs = (int*)(bias + 256);
    int tid = threadIdx.x;
    long long rb = (long long)blockIdx.x * 64;

    for (int i = tid * 4; i < 8192; i += 1024) {
        size_t flat = (size_t)rb * 128 + i;          // multiple of 4
        if (flat < (size_t)NPTS * 128)
            *(float4*)&As[i] = *(const float4*)&g_pf2[flat];
        else
            *(float4*)&As[i] = make_float4(0.f, 0.f, 0.f, 0.f);
    }
    if (tid < 64) {
        long long row = rb + tid;
        idxs[tid] = (row < NPTS) ? load_idx(idxp, row, g_idx_is64) : 0;
    }
    bias[tid] = b4[tid];
    __syncthreads();

    int cx = (tid & 31) * 4;
    int r0 = (tid >> 5) * 8;

    // Phase 1: Bs = relu(As @ W3[128:256,:] + g3[idx])
    {
        float acc[8][8];
        #pragma unroll
        for (int i = 0; i < 8; i++)
            #pragma unroll
            for (int j = 0; j < 8; j++) acc[i][j] = 0.f;

        gemm_dbuf(As, 128, W3 + 128 * 256, 128, Ws, r0, cx, tid, acc);

        #pragma unroll
        for (int i = 0; i < 8; i++) {
            const float* g3r = g_g3 + (size_t)idxs[r0 + i] * 256;
            #pragma unroll
            for (int j = 0; j < 8; j++) {
                int col = col_of(cx, j);
                Bs[(r0 + i) * 256 + col] = fmaxf(acc[i][j] + g3r[col], 0.f);
            }
        }
    }
    __syncthreads();

    // Phase 2: pf5 = relu(Bs @ W4 + b4); scatter-max into g_vox2
    {
        float acc[8][8];
        #pragma unroll
        for (int i = 0; i < 8; i++)
            #pragma unroll
            for (int j = 0; j < 8; j++) acc[i][j] = 0.f;

        gemm_dbuf(Bs, 256, W4, 256, Ws, r0, cx, tid, acc);

        #pragma unroll
        for (int i = 0; i < 8; i++) {
            long long row = rb + r0 + i;
            if (row >= NPTS) continue;
            float* vr = g_vox2 + (size_t)idxs[r0 + i] * 256;
            #pragma unroll
            for (int j = 0; j < 8; j++) {
                int col = col_of(cx, j);
                float v = fmaxf(acc[i][j] + bias[col], 0.f);
                if (v > vr[col]) atomicMax((int*)&vr[col], __float_as_int(v));
            }
        }
    }
}

// ---------------- K4: out = relu(vox2 @ Wv2 + bv2) --------------------------
// smem floats: As 64*256 | Ws 2*4096 | bias 256
#define K4_SMEM_FLOATS (16384 + 8192 + 256)

__global__ void k4(const float* __restrict__ Wv2, const float* __restrict__ bv2,
                   float* __restrict__ out) {
    extern __shared__ float sm[];
    float* As = sm;               // [64][256]
    float* Ws = As + 16384;       // 2*[16][256]
    float* bias = Ws + 8192;      // 256
    int tid = threadIdx.x;
    int vb = blockIdx.x * 64;

    for (int i = tid * 4; i < 16384; i += 1024)
        *(float4*)&As[i] = *(const float4*)&g_vox2[(size_t)vb * 256 + i];
    bias[tid] = bv2[tid];
    __syncthreads();

    int cx = (tid & 31) * 4;
    int r0 = (tid >> 5) * 8;
    float acc[8][8];
    #pragma unroll
    for (int i = 0; i < 8; i++)
        #pragma unroll
        for (int j = 0; j < 8; j++) acc[i][j] = 0.f;

    gemm_dbuf(As, 256, Wv2, 256, Ws, r0, cx, tid, acc);

    #pragma unroll
    for (int i = 0; i < 8; i++) {
        float* o = out + (size_t)(vb + r0 + i) * 256;
        #pragma unroll
        for (int j = 0; j < 8; j++) {
            int col = col_of(cx, j);
            o[col] = fmaxf(acc[i][j] + bias[col], 0.f);
        }
    }
}

// ---------------- launch ----------------------------------------------------
extern "C" void kernel_launch(void* const* d_in, const int* in_sizes, int n_in,
                              void* d_out, int out_size) {
    const float* inp  = (const float*)d_in[0];
    const void*  idxp = d_in[1];
    const float* W1   = (const float*)d_in[2];
    const float* b1   = (const float*)d_in[3];
    const float* W2   = (const float*)d_in[4];
    const float* b2   = (const float*)d_in[5];
    const float* Wv1  = (const float*)d_in[6];
    const float* bv1  = (const float*)d_in[7];
    const float* W3   = (const float*)d_in[8];
    const float* b3   = (const float*)d_in[9];
    const float* W4   = (const float*)d_in[10];
    const float* b4   = (const float*)d_in[11];
    const float* Wv2  = (const float*)d_in[12];
    const float* bv2  = (const float*)d_in[13];

    size_t sm1 = K1_SMEM_FLOATS * 4;
    size_t sm2 = K2_SMEM_FLOATS * 4;
    size_t sm3 = K3_SMEM_BYTES;
    size_t sm4 = K4_SMEM_FLOATS * 4;
    cudaFuncSetAttribute(k1, cudaFuncAttributeMaxDynamicSharedMemorySize, (int)sm1);
    cudaFuncSetAttribute(k2, cudaFuncAttributeMaxDynamicSharedMemorySize, (int)sm2);
    cudaFuncSetAttribute(k3, cudaFuncAttributeMaxDynamicSharedMemorySize, (int)sm3);
    cudaFuncSetAttribute(k4, cudaFuncAttributeMaxDynamicSharedMemorySize, (int)sm4);

    void *p1, *p2;
    cudaGetSymbolAddress(&p1, g_vox1);
    cudaGetSymbolAddress(&p2, g_vox2);
    cudaMemsetAsync(p1, 0, (size_t)NVOX * 128 * 4);
    cudaMemsetAsync(p2, 0, (size_t)NVOX * 256 * 4);

    kdetect<<<1, 256>>>((const unsigned*)idxp);
    k1<<<(NPTS + 255) / 256, 256, sm1>>>(inp, idxp, W1, b1, W2, b2);
    k2<<<NVOX / 64, 256, sm2>>>(Wv1, bv1, W3, b3);
    k3<<<(NPTS + 63) / 64, 256, sm3>>>(idxp, W3, W4, b4);
    k4<<<NVOX / 64, 256, sm4>>>(Wv2, bv2, (float*)d_out);
}

// round 7
// speedup vs baseline: 1.0502x; 1.0502x over previous
#include <cuda_runtime.h>
#include <cstdint>
#include <cstddef>

#define NPTS 500000
#define NVOX 65536

// ---------------- scratch (device globals; no allocations allowed) ----------
__device__ float g_pf2 [(size_t)NPTS * 128];   // 256 MB  relu(point MLP2)
__device__ float g_vox1[(size_t)NVOX * 128];   //  32 MB  segment-max #1 (init 0)
__device__ float g_g3  [(size_t)NVOX * 256];   //  64 MB  voxf @ W3_top + b3
__device__ float g_vox2[(size_t)NVOX * 256];   //  64 MB  segment-max #2 (init 0)
__device__ int   g_idx_is64;

// ---------------- idx dtype probe (int64 vs int32 delivery) -----------------
__global__ void kdetect(const unsigned* __restrict__ raw) {
    unsigned w = raw[threadIdx.x * 2 + 1];               // first 2KB only (safe)
    unsigned any = __ballot_sync(0xffffffffu, w != 0u);
    __shared__ int s[8];
    if ((threadIdx.x & 31) == 0) s[threadIdx.x >> 5] = (any != 0u);
    __syncthreads();
    if (threadIdx.x == 0) {
        int t = 0;
        #pragma unroll
        for (int i = 0; i < 8; i++) t |= s[i];
        g_idx_is64 = !t;
    }
}

__device__ __forceinline__ int load_idx(const void* idxp, long long row, int is64) {
    return is64 ? (int)((const long long*)idxp)[row] : ((const int*)idxp)[row];
}

// ---------------- K1: inp -> pf1 -> pf2 (store) + scatter-max vox1 ----------
// smem floats: W1s 384 | b1s 64 | W2s 8192 | b2s 128
#define K1_SMEM_FLOATS (384 + 64 + 8192 + 128)

__global__ void __launch_bounds__(256, 2)
k1(const float* __restrict__ inp, const void* __restrict__ idxp,
   const float* __restrict__ W1, const float* __restrict__ b1,
   const float* __restrict__ W2, const float* __restrict__ b2) {
    extern __shared__ float sm[];
    float* W1s = sm;                 // 6*64
    float* b1s = W1s + 384;          // 64
    float* W2s = b1s + 64;           // 64*128
    float* b2s = W2s + 8192;         // 128
    int tid = threadIdx.x;

    for (int i = tid; i < 384; i += 256) W1s[i] = W1[i];
    if (tid < 64)  b1s[tid] = b1[tid];
    for (int i = tid; i < 8192; i += 256) W2s[i] = W2[i];
    if (tid < 128) b2s[tid] = b2[tid];
    __syncthreads();

    long long p = (long long)blockIdx.x * 256 + tid;
    if (p >= NPTS) return;
    const int is64 = g_idx_is64;

    float x[6];
    #pragma unroll
    for (int c = 0; c < 6; c++) x[c] = inp[p * 6 + c];

    float pf1[64];
    #pragma unroll
    for (int j = 0; j < 64; j++) {
        float a = b1s[j];
        #pragma unroll
        for (int c = 0; c < 6; c++) a = fmaf(x[c], W1s[c * 64 + j], a);
        pf1[j] = fmaxf(a, 0.f);
    }

    long long vox = load_idx(idxp, p, is64);
    float* dst = g_pf2 + (size_t)p * 128;
    float* vdst = g_vox1 + (size_t)vox * 128;

    #pragma unroll
    for (int cj = 0; cj < 4; cj++) {
        float acc[32];
        #pragma unroll
        for (int j = 0; j < 32; j++) acc[j] = b2s[cj * 32 + j];
        #pragma unroll
        for (int k = 0; k < 64; k++) {
            float pv = pf1[k];
            const float* wr = &W2s[k * 128 + cj * 32];
            #pragma unroll
            for (int j = 0; j < 32; j++) acc[j] = fmaf(pv, wr[j], acc[j]);
        }
        #pragma unroll
        for (int j = 0; j < 32; j++) acc[j] = fmaxf(acc[j], 0.f);
        #pragma unroll
        for (int j4 = 0; j4 < 8; j4++)
            *(float4*)&dst[cj * 32 + j4 * 4] =
                make_float4(acc[j4*4+0], acc[j4*4+1], acc[j4*4+2], acc[j4*4+3]);
        #pragma unroll
        for (int j = 0; j < 32; j++) {
            float v = acc[j];
            if (v > vdst[cj * 32 + j])
                atomicMax((int*)&vdst[cj * 32 + j], __float_as_int(v));
        }
    }
}

// ---------------- shared GEMM helpers (256 threads, 64-row tiles) -----------
__device__ __forceinline__ void mma16_8x8(const float* __restrict__ A, int lda, int ks,
                                          const float* __restrict__ Ws,
                                          int r0, int cx, float (&acc)[8][8]) {
    #pragma unroll
    for (int k4 = 0; k4 < 4; k4++) {
        float4 a4[8];
        #pragma unroll
        for (int i = 0; i < 8; i++)
            a4[i] = *(const float4*)&A[(r0 + i) * lda + ks + k4 * 4];
        #pragma unroll
        for (int kk = 0; kk < 4; kk++) {
            float4 bA = *(const float4*)&Ws[(k4 * 4 + kk) * 256 + cx];
            float4 bB = *(const float4*)&Ws[(k4 * 4 + kk) * 256 + 128 + cx];
            float b[8] = {bA.x, bA.y, bA.z, bA.w, bB.x, bB.y, bB.z, bB.w};
            #pragma unroll
            for (int i = 0; i < 8; i++) {
                float av = (kk == 0) ? a4[i].x : (kk == 1) ? a4[i].y
                         : (kk == 2) ? a4[i].z : a4[i].w;
                #pragma unroll
                for (int j = 0; j < 8; j++) acc[i][j] = fmaf(av, b[j], acc[i][j]);
            }
        }
    }
}

__device__ __forceinline__ int col_of(int cx, int j) {
    return (j < 4) ? (cx + j) : (128 + cx + (j - 4));
}

__device__ __forceinline__ void ldg_w256(float (&r)[16], const float* __restrict__ W,
                                         int ks, int tid) {
    #pragma unroll
    for (int t = 0; t < 16; t++) {
        int i = tid + t * 256;
        r[t] = W[(size_t)(ks + (i >> 8)) * 256 + (i & 255)];
    }
}
__device__ __forceinline__ void sts_w256(float* Ws, const float (&r)[16], int tid) {
    #pragma unroll
    for (int t = 0; t < 16; t++) Ws[tid + t * 256] = r[t];
}

// Double-buffered K-loop; Ws = 2*4096 floats (may alias a dead tile region;
// caller guarantees A does not overlap Ws). Ends WITHOUT trailing sync.
__device__ __forceinline__ void gemm_dbuf(const float* __restrict__ A, int lda,
                                          const float* __restrict__ W, int KTOT,
                                          float* Ws, int r0, int cx, int tid,
                                          float (&acc)[8][8]) {
    const int T = KTOT / 16;
    float wreg[16];
    ldg_w256(wreg, W, 0, tid);
    sts_w256(Ws, wreg, tid);
    __syncthreads();
    for (int t = 0; t < T; t++) {
        float* cur  = Ws + (t & 1) * 4096;
        float* next = Ws + ((t + 1) & 1) * 4096;
        if (t + 1 < T) ldg_w256(wreg, W, (t + 1) * 16, tid);
        mma16_8x8(A, lda, t * 16, cur, r0, cx, acc);
        if (t + 1 < T) {
            sts_w256(next, wreg, tid);
            __syncthreads();
        }
    }
}

// ---------------- K2: vox1 -> voxf(relu,Wv1,bv1) -> g3 = voxf@W3top + b3 ----
// smem floats: As 8192 | Bs 8192 | bias 256   (Ws aliases: ph1 in Bs, ph2 in As)
#define K2_SMEM_FLOATS (8192 + 8192 + 256)

__global__ void __launch_bounds__(256, 2)
k2(const float* __restrict__ Wv1, const float* __restrict__ bv1,
   const float* __restrict__ W3, const float* __restrict__ b3) {
    extern __shared__ float sm[];
    float* As = sm;               // [64][128]
    float* Bs = As + 8192;        // [64][128]; phase-1 Ws aliases here
    float* bias = Bs + 8192;      // 256
    int tid = threadIdx.x;
    int vb = blockIdx.x * 64;

    for (int i = tid * 4; i < 8192; i += 1024)
        *(float4*)&As[i] = *(const float4*)&g_vox1[(size_t)vb * 128 + i];
    if (tid < 128) bias[tid] = bv1[tid];
    __syncthreads();

    // Phase 1: Bs = relu(As @ Wv1 + bv1)  M=64 N=128 K=128 ; Ws inside Bs
    {
        float* Ws = Bs;                   // 2048 floats per tile, single buffer
        int cx = (tid & 15) * 4;
        int r0 = (tid >> 4) * 4;
        float acc[4][8];
        #pragma unroll
        for (int i = 0; i < 4; i++)
            #pragma unroll
            for (int j = 0; j < 8; j++) acc[i][j] = 0.f;

        for (int ks = 0; ks < 128; ks += 16) {
            for (int i = tid; i < 2048; i += 256)
                Ws[i] = Wv1[(size_t)(ks + (i >> 7)) * 128 + (i & 127)];
            __syncthreads();
            #pragma unroll
            for (int k4 = 0; k4 < 4; k4++) {
                float4 a4[4];
                #pragma unroll
                for (int i = 0; i < 4; i++)
                    a4[i] = *(const float4*)&As[(r0 + i) * 128 + ks + k4 * 4];
                #pragma unroll
                for (int kk = 0; kk < 4; kk++) {
                    float4 bA = *(const float4*)&Ws[(k4 * 4 + kk) * 128 + cx];
                    float4 bB = *(const float4*)&Ws[(k4 * 4 + kk) * 128 + 64 + cx];
                    float b[8] = {bA.x, bA.y, bA.z, bA.w, bB.x, bB.y, bB.z, bB.w};
                    #pragma unroll
                    for (int i = 0; i < 4; i++) {
                        float av = (kk == 0) ? a4[i].x : (kk == 1) ? a4[i].y
                                 : (kk == 2) ? a4[i].z : a4[i].w;
                        #pragma unroll
                        for (int j = 0; j < 8; j++)
                            acc[i][j] = fmaf(av, b[j], acc[i][j]);
                    }
                }
            }
            __syncthreads();   // protects Ws reuse AND final Bs overwrite below
        }
        #pragma unroll
        for (int i = 0; i < 4; i++)
            #pragma unroll
            for (int j = 0; j < 8; j++) {
                int col = (j < 4) ? (cx + j) : (64 + cx + (j - 4));
                Bs[(r0 + i) * 128 + col] = fmaxf(acc[i][j] + bias[col], 0.f);
            }
    }
    __syncthreads();
    bias[tid] = b3[tid];   // published by gemm_dbuf's first __syncthreads

    // Phase 2: g3 = Bs @ W3[0:128,:] + b3 ; Ws aliases As (dead)
    {
        int cx = (tid & 31) * 4;
        int r0 = (tid >> 5) * 8;
        float acc[8][8];
        #pragma unroll
        for (int i = 0; i < 8; i++)
            #pragma unroll
            for (int j = 0; j < 8; j++) acc[i][j] = 0.f;

        gemm_dbuf(Bs, 128, W3, 128, As, r0, cx, tid, acc);

        #pragma unroll
        for (int i = 0; i < 8; i++) {
            float* out = g_g3 + (size_t)(vb + r0 + i) * 256;
            #pragma unroll
            for (int j = 0; j < 8; j++) {
                int col = col_of(cx, j);
                out[col] = acc[i][j] + bias[col];
            }
        }
    }
}

// ---------------- K3: pf2 -> (@W3bot + g3[idx], relu) -> (@W4+b4, relu) -> max
// smem floats: As 8192 | Bs 16384 | bias 256 | idxs 64
// (phase-1 Ws aliases Bs; phase-2 Ws aliases As)
#define K3_SMEM_BYTES ((8192 + 16384 + 256) * 4 + 64 * 4)

__global__ void __launch_bounds__(256, 2)
k3(const void* __restrict__ idxp,
   const float* __restrict__ W3, const float* __restrict__ W4,
   const float* __restrict__ b4) {
    extern __shared__ float sm[];
    float* As = sm;                // [64][128] pf2 tile ; phase-2 Ws alias
    float* Bs = As + 8192;         // [64][256] pf4 tile ; phase-1 Ws alias
    float* bias = Bs + 16384;      // 256 (b4)
    int* idxs = (int*)(bias + 256);
    int tid = threadIdx.x;
    long long rb = (long long)blockIdx.x * 64;

    for (int i = tid * 4; i < 8192; i += 1024) {
        size_t flat = (size_t)rb * 128 + i;          // multiple of 4
        if (flat < (size_t)NPTS * 128)
            *(float4*)&As[i] = *(const float4*)&g_pf2[flat];
        else
            *(float4*)&As[i] = make_float4(0.f, 0.f, 0.f, 0.f);
    }
    if (tid < 64) {
        long long row = rb + tid;
        idxs[tid] = (row < NPTS) ? load_idx(idxp, row, g_idx_is64) : 0;
    }
    bias[tid] = b4[tid];
    __syncthreads();

    int cx = (tid & 31) * 4;
    int r0 = (tid >> 5) * 8;

    // Phase 1: Bs = relu(As @ W3[128:256,:] + g3[idx]) ; Ws inside Bs
    {
        float acc[8][8];
        #pragma unroll
        for (int i = 0; i < 8; i++)
            #pragma unroll
            for (int j = 0; j < 8; j++) acc[i][j] = 0.f;

        gemm_dbuf(As, 128, W3 + 128 * 256, 128, Bs, r0, cx, tid, acc);
        __syncthreads();   // all Ws reads done before Bs epilogue overwrite

        #pragma unroll
        for (int i = 0; i < 8; i++) {
            const float* g3r = g_g3 + (size_t)idxs[r0 + i] * 256;
            #pragma unroll
            for (int j = 0; j < 8; j++) {
                int col = col_of(cx, j);
                Bs[(r0 + i) * 256 + col] = fmaxf(acc[i][j] + g3r[col], 0.f);
            }
        }
    }
    __syncthreads();

    // Phase 2: pf5 = relu(Bs @ W4 + b4) ; Ws aliases As (dead) ; scatter-max
    {
        float acc[8][8];
        #pragma unroll
        for (int i = 0; i < 8; i++)
            #pragma unroll
            for (int j = 0; j < 8; j++) acc[i][j] = 0.f;

        gemm_dbuf(Bs, 256, W4, 256, As, r0, cx, tid, acc);

        #pragma unroll
        for (int i = 0; i < 8; i++) {
            long long row = rb + r0 + i;
            if (row >= NPTS) continue;
            float* vr = g_vox2 + (size_t)idxs[r0 + i] * 256;
            #pragma unroll
            for (int j = 0; j < 8; j++) {
                int col = col_of(cx, j);
                float v = fmaxf(acc[i][j] + bias[col], 0.f);
                if (v > vr[col]) atomicMax((int*)&vr[col], __float_as_int(v));
            }
        }
    }
}

// ---------------- K4: out = relu(vox2 @ Wv2 + bv2) --------------------------
// smem floats: As 16384 | Ws 8192 | bias 256
#define K4_SMEM_FLOATS (16384 + 8192 + 256)

__global__ void __launch_bounds__(256, 2)
k4(const float* __restrict__ Wv2, const float* __restrict__ bv2,
   float* __restrict__ out) {
    extern __shared__ float sm[];
    float* As = sm;               // [64][256]
    float* Ws = As + 16384;       // 2*[16][256]
    float* bias = Ws + 8192;      // 256
    int tid = threadIdx.x;
    int vb = blockIdx.x * 64;

    for (int i = tid * 4; i < 16384; i += 1024)
        *(float4*)&As[i] = *(const float4*)&g_vox2[(size_t)vb * 256 + i];
    bias[tid] = bv2[tid];
    __syncthreads();

    int cx = (tid & 31) * 4;
    int r0 = (tid >> 5) * 8;
    float acc[8][8];
    #pragma unroll
    for (int i = 0; i < 8; i++)
        #pragma unroll
        for (int j = 0; j < 8; j++) acc[i][j] = 0.f;

    gemm_dbuf(As, 256, Wv2, 256, Ws, r0, cx, tid, acc);

    #pragma unroll
    for (int i = 0; i < 8; i++) {
        float* o = out + (size_t)(vb + r0 + i) * 256;
        #pragma unroll
        for (int j = 0; j < 8; j++) {
            int col = col_of(cx, j);
            o[col] = fmaxf(acc[i][j] + bias[col], 0.f);
        }
    }
}

// ---------------- launch ----------------------------------------------------
extern "C" void kernel_launch(void* const* d_in, const int* in_sizes, int n_in,
                              void* d_out, int out_size) {
    const float* inp  = (const float*)d_in[0];
    const void*  idxp = d_in[1];
    const float* W1   = (const float*)d_in[2];
    const float* b1   = (const float*)d_in[3];
    const float* W2   = (const float*)d_in[4];
    const float* b2   = (const float*)d_in[5];
    const float* Wv1  = (const float*)d_in[6];
    const float* bv1  = (const float*)d_in[7];
    const float* W3   = (const float*)d_in[8];
    const float* b3   = (const float*)d_in[9];
    const float* W4   = (const float*)d_in[10];
    const float* b4   = (const float*)d_in[11];
    const float* Wv2  = (const float*)d_in[12];
    const float* bv2  = (const float*)d_in[13];

    size_t sm1 = K1_SMEM_FLOATS * 4;
    size_t sm2 = K2_SMEM_FLOATS * 4;
    size_t sm3 = K3_SMEM_BYTES;
    size_t sm4 = K4_SMEM_FLOATS * 4;
    cudaFuncSetAttribute(k1, cudaFuncAttributeMaxDynamicSharedMemorySize, (int)sm1);
    cudaFuncSetAttribute(k2, cudaFuncAttributeMaxDynamicSharedMemorySize, (int)sm2);
    cudaFuncSetAttribute(k3, cudaFuncAttributeMaxDynamicSharedMemorySize, (int)sm3);
    cudaFuncSetAttribute(k4, cudaFuncAttributeMaxDynamicSharedMemorySize, (int)sm4);

    void *p1, *p2;
    cudaGetSymbolAddress(&p1, g_vox1);
    cudaGetSymbolAddress(&p2, g_vox2);
    cudaMemsetAsync(p1, 0, (size_t)NVOX * 128 * 4);
    cudaMemsetAsync(p2, 0, (size_t)NVOX * 256 * 4);

    kdetect<<<1, 256>>>((const unsigned*)idxp);
    k1<<<(NPTS + 255) / 256, 256, sm1>>>(inp, idxp, W1, b1, W2, b2);
    k2<<<NVOX / 64, 256, sm2>>>(Wv1, bv1, W3, b3);
    k3<<<(NPTS + 63) / 64, 256, sm3>>>(idxp, W3, W4, b4);
    k4<<<NVOX / 64, 256, sm4>>>(Wv2, bv2, (float*)d_out);
}

// round 9
// speedup vs baseline: 1.7652x; 1.6808x over previous
#include <cuda_runtime.h>
#include <cstdint>
#include <cstddef>

#define NPTS 500000
#define NVOX 65536

typedef unsigned long long u64;

// ---------------- packed f32x2 helpers (FFMA2: 2 fp32 FMA per issue) --------
__device__ __forceinline__ u64 fma2(u64 a, u64 b, u64 c) {
    u64 d;
    asm("fma.rn.f32x2 %0, %1, %2, %3;" : "=l"(d) : "l"(a), "l"(b), "l"(c));
    return d;
}
__device__ __forceinline__ u64 dup2(float v) {
    u64 d;
    asm("mov.b64 %0, {%1, %1};" : "=l"(d) : "f"(v));
    return d;
}
__device__ __forceinline__ void unpack2(float& lo, float& hi, u64 v) {
    asm("mov.b64 {%0, %1}, %2;" : "=f"(lo), "=f"(hi) : "l"(v));
}

// ---------------- scratch (device globals; no allocations allowed) ----------
__device__ float g_pf2 [(size_t)NPTS * 128];   // 256 MB  relu(point MLP2)
__device__ float g_vox1[(size_t)NVOX * 128];   //  32 MB  segment-max #1 (init 0)
__device__ float g_g3  [(size_t)NVOX * 256];   //  64 MB  voxf @ W3_top + b3
__device__ float g_vox2[(size_t)NVOX * 256];   //  64 MB  segment-max #2 (init 0)
__device__ int   g_idx_is64;

// ---------------- idx dtype probe (int64 vs int32 delivery) -----------------
__global__ void kdetect(const unsigned* __restrict__ raw) {
    unsigned w = raw[threadIdx.x * 2 + 1];               // first 2KB only (safe)
    unsigned any = __ballot_sync(0xffffffffu, w != 0u);
    __shared__ int s[8];
    if ((threadIdx.x & 31) == 0) s[threadIdx.x >> 5] = (any != 0u);
    __syncthreads();
    if (threadIdx.x == 0) {
        int t = 0;
        #pragma unroll
        for (int i = 0; i < 8; i++) t |= s[i];
        g_idx_is64 = !t;
    }
}

__device__ __forceinline__ int load_idx(const void* idxp, long long row, int is64) {
    return is64 ? (int)((const long long*)idxp)[row] : ((const int*)idxp)[row];
}

// ---------------- K1: inp -> pf1 -> pf2 (store) + scatter-max vox1 ----------
// smem floats: W1s 384 | b1s 64 | W2s 8192 | b2s 128
#define K1_SMEM_FLOATS (384 + 64 + 8192 + 128)

__global__ void __launch_bounds__(256, 2)
k1(const float* __restrict__ inp, const void* __restrict__ idxp,
   const float* __restrict__ W1, const float* __restrict__ b1,
   const float* __restrict__ W2, const float* __restrict__ b2) {
    extern __shared__ float sm[];
    float* W1s = sm;                 // 6*64
    float* b1s = W1s + 384;          // 64
    float* W2s = b1s + 64;           // 64*128
    float* b2s = W2s + 8192;         // 128
    int tid = threadIdx.x;

    for (int i = tid; i < 384; i += 256) W1s[i] = W1[i];
    if (tid < 64)  b1s[tid] = b1[tid];
    for (int i = tid; i < 8192; i += 256) W2s[i] = W2[i];
    if (tid < 128) b2s[tid] = b2[tid];
    __syncthreads();

    long long p = (long long)blockIdx.x * 256 + tid;
    if (p >= NPTS) return;
    const int is64 = g_idx_is64;

    float x[6];
    #pragma unroll
    for (int c = 0; c < 6; c++) x[c] = inp[p * 6 + c];

    float pf1[64];
    #pragma unroll
    for (int j = 0; j < 64; j++) {
        float a = b1s[j];
        #pragma unroll
        for (int c = 0; c < 6; c++) a = fmaf(x[c], W1s[c * 64 + j], a);
        pf1[j] = fmaxf(a, 0.f);
    }

    long long vox = load_idx(idxp, p, is64);
    float* dst = g_pf2 + (size_t)p * 128;
    float* vdst = g_vox1 + (size_t)vox * 128;

    #pragma unroll
    for (int cj = 0; cj < 4; cj++) {
        // acc pairs over adjacent j: acc2[jp] = (acc[2jp], acc[2jp+1])
        u64 acc2[16];
        #pragma unroll
        for (int m = 0; m < 8; m++) {
            ulonglong2 bp = *(const ulonglong2*)&b2s[cj * 32 + m * 4];
            acc2[2*m]   = bp.x;
            acc2[2*m+1] = bp.y;
        }
        #pragma unroll
        for (int k = 0; k < 64; k++) {
            u64 pd = dup2(pf1[k]);
            const float* wr = &W2s[k * 128 + cj * 32];
            #pragma unroll
            for (int m = 0; m < 8; m++) {
                ulonglong2 w2 = *(const ulonglong2*)&wr[m * 4];
                acc2[2*m]   = fma2(pd, w2.x, acc2[2*m]);
                acc2[2*m+1] = fma2(pd, w2.y, acc2[2*m+1]);
            }
        }
        float acc[32];
        #pragma unroll
        for (int jp = 0; jp < 16; jp++) {
            float lo, hi;
            unpack2(lo, hi, acc2[jp]);
            acc[2*jp]   = fmaxf(lo, 0.f);
            acc[2*jp+1] = fmaxf(hi, 0.f);
        }
        #pragma unroll
        for (int j4 = 0; j4 < 8; j4++)
            *(float4*)&dst[cj * 32 + j4 * 4] =
                make_float4(acc[j4*4+0], acc[j4*4+1], acc[j4*4+2], acc[j4*4+3]);
        #pragma unroll
        for (int j = 0; j < 32; j++) {
            float v = acc[j];
            if (v > vdst[cj * 32 + j])
                atomicMax((int*)&vdst[cj * 32 + j], __float_as_int(v));
        }
    }
}

// ---------------- shared GEMM helpers (256 threads, 64-row tiles) -----------
// acc2[i][j2]: j2=0..3 packs cols {cx,cx+1},{cx+2,cx+3},{128+cx,128+cx+1},
// {128+cx+2,128+cx+3}. A values broadcast-duplicated via mov.b64.
__device__ __forceinline__ void mma16_8x8_x2(const float* __restrict__ A, int lda,
                                             int ks, const float* __restrict__ Ws,
                                             int r0, int cx, u64 (&acc2)[8][4]) {
    #pragma unroll
    for (int q = 0; q < 4; q++) {
        float4 a4[8];
        #pragma unroll
        for (int i = 0; i < 8; i++)
            a4[i] = *(const float4*)&A[(r0 + i) * lda + ks + q * 4];
        #pragma unroll
        for (int kk = 0; kk < 4; kk++) {
            const float* wr = &Ws[(q * 4 + kk) * 256];
            ulonglong2 bA = *(const ulonglong2*)&wr[cx];        // j2=0,1
            ulonglong2 bB = *(const ulonglong2*)&wr[128 + cx];  // j2=2,3
            #pragma unroll
            for (int i = 0; i < 8; i++) {
                float av = (kk == 0) ? a4[i].x : (kk == 1) ? a4[i].y
                         : (kk == 2) ? a4[i].z : a4[i].w;
                u64 ad = dup2(av);
                acc2[i][0] = fma2(ad, bA.x, acc2[i][0]);
                acc2[i][1] = fma2(ad, bA.y, acc2[i][1]);
                acc2[i][2] = fma2(ad, bB.x, acc2[i][2]);
                acc2[i][3] = fma2(ad, bB.y, acc2[i][3]);
            }
        }
    }
}

// col of pair j2, half h (h=0 low/first float)
__device__ __forceinline__ int col_of2(int cx, int j2, int h) {
    return ((j2 < 2) ? (cx + 2 * j2) : (128 + cx + 2 * (j2 - 2))) + h;
}

__device__ __forceinline__ void ldg_w256(float (&r)[16], const float* __restrict__ W,
                                         int ks, int tid) {
    #pragma unroll
    for (int t = 0; t < 16; t++) {
        int i = tid + t * 256;
        r[t] = W[(size_t)(ks + (i >> 8)) * 256 + (i & 255)];
    }
}
__device__ __forceinline__ void sts_w256(float* Ws, const float (&r)[16], int tid) {
    #pragma unroll
    for (int t = 0; t < 16; t++) Ws[tid + t * 256] = r[t];
}

// Double-buffered K-loop; Ws = 2*4096 floats (may alias a dead tile region;
// caller guarantees A does not overlap Ws). Ends WITHOUT trailing sync.
__device__ __forceinline__ void gemm_dbuf(const float* __restrict__ A, int lda,
                                          const float* __restrict__ W, int KTOT,
                                          float* Ws, int r0, int cx, int tid,
                                          u64 (&acc2)[8][4]) {
    const int T = KTOT / 16;
    float wreg[16];
    ldg_w256(wreg, W, 0, tid);
    sts_w256(Ws, wreg, tid);
    __syncthreads();
    for (int t = 0; t < T; t++) {
        float* cur  = Ws + (t & 1) * 4096;
        float* next = Ws + ((t + 1) & 1) * 4096;
        if (t + 1 < T) ldg_w256(wreg, W, (t + 1) * 16, tid);
        mma16_8x8_x2(A, lda, t * 16, cur, r0, cx, acc2);
        if (t + 1 < T) {
            sts_w256(next, wreg, tid);
            __syncthreads();
        }
    }
}

// ---------------- K2: vox1 -> voxf(relu,Wv1,bv1) -> g3 = voxf@W3top + b3 ----
// smem floats: As 8192 | Bs 8192 | bias 256   (Ws aliases: ph1 in Bs, ph2 in As)
#define K2_SMEM_FLOATS (8192 + 8192 + 256)

__global__ void __launch_bounds__(256, 2)
k2(const float* __restrict__ Wv1, const float* __restrict__ bv1,
   const float* __restrict__ W3, const float* __restrict__ b3) {
    extern __shared__ float sm[];
    float* As = sm;               // [64][128]
    float* Bs = As + 8192;        // [64][128]; phase-1 Ws aliases here
    float* bias = Bs + 8192;      // 256
    int tid = threadIdx.x;
    int vb = blockIdx.x * 64;

    for (int i = tid * 4; i < 8192; i += 1024)
        *(float4*)&As[i] = *(const float4*)&g_vox1[(size_t)vb * 128 + i];
    if (tid < 128) bias[tid] = bv1[tid];
    __syncthreads();

    // Phase 1: Bs = relu(As @ Wv1 + bv1)  M=64 N=128 K=128 ; Ws inside Bs
    {
        float* Ws = Bs;                   // 2048 floats per tile, single buffer
        int cx = (tid & 15) * 4;
        int r0 = (tid >> 4) * 4;
        float acc[4][8];
        #pragma unroll
        for (int i = 0; i < 4; i++)
            #pragma unroll
            for (int j = 0; j < 8; j++) acc[i][j] = 0.f;

        for (int ks = 0; ks < 128; ks += 16) {
            for (int i = tid; i < 2048; i += 256)
                Ws[i] = Wv1[(size_t)(ks + (i >> 7)) * 128 + (i & 127)];
            __syncthreads();
            #pragma unroll
            for (int k4 = 0; k4 < 4; k4++) {
                float4 a4[4];
                #pragma unroll
                for (int i = 0; i < 4; i++)
                    a4[i] = *(const float4*)&As[(r0 + i) * 128 + ks + k4 * 4];
                #pragma unroll
                for (int kk = 0; kk < 4; kk++) {
                    float4 bA = *(const float4*)&Ws[(k4 * 4 + kk) * 128 + cx];
                    float4 bB = *(const float4*)&Ws[(k4 * 4 + kk) * 128 + 64 + cx];
                    float b[8] = {bA.x, bA.y, bA.z, bA.w, bB.x, bB.y, bB.z, bB.w};
                    #pragma unroll
                    for (int i = 0; i < 4; i++) {
                        float av = (kk == 0) ? a4[i].x : (kk == 1) ? a4[i].y
                                 : (kk == 2) ? a4[i].z : a4[i].w;
                        #pragma unroll
                        for (int j = 0; j < 8; j++)
                            acc[i][j] = fmaf(av, b[j], acc[i][j]);
                    }
                }
            }
            __syncthreads();   // protects Ws reuse AND final Bs overwrite below
        }
        #pragma unroll
        for (int i = 0; i < 4; i++)
            #pragma unroll
            for (int j = 0; j < 8; j++) {
                int col = (j < 4) ? (cx + j) : (64 + cx + (j - 4));
                Bs[(r0 + i) * 128 + col] = fmaxf(acc[i][j] + bias[col], 0.f);
            }
    }
    __syncthreads();
    bias[tid] = b3[tid];   // published by gemm_dbuf's first __syncthreads

    // Phase 2: g3 = Bs @ W3[0:128,:] + b3 ; Ws aliases As (dead)
    {
        int cx = (tid & 31) * 4;
        int r0 = (tid >> 5) * 8;
        u64 acc2[8][4];
        #pragma unroll
        for (int i = 0; i < 8; i++)
            #pragma unroll
            for (int j = 0; j < 4; j++) acc2[i][j] = 0ull;

        gemm_dbuf(Bs, 128, W3, 128, As, r0, cx, tid, acc2);

        #pragma unroll
        for (int i = 0; i < 8; i++) {
            float* out = g_g3 + (size_t)(vb + r0 + i) * 256;
            #pragma unroll
            for (int j2 = 0; j2 < 4; j2++) {
                float lo, hi;
                unpack2(lo, hi, acc2[i][j2]);
                int c0 = col_of2(cx, j2, 0);
                out[c0]     = lo + bias[c0];
                out[c0 + 1] = hi + bias[c0 + 1];
            }
        }
    }
}

// ---------------- K3: pf2 -> (@W3bot + g3[idx], relu) -> (@W4+b4, relu) -> max
// smem floats: As 8192 | Bs 16384 | bias 256 | idxs 64
// (phase-1 Ws aliases Bs; phase-2 Ws aliases As)
#define K3_SMEM_BYTES ((8192 + 16384 + 256) * 4 + 64 * 4)

__global__ void __launch_bounds__(256, 2)
k3(const void* __restrict__ idxp,
   const float* __restrict__ W3, const float* __restrict__ W4,
   const float* __restrict__ b4) {
    extern __shared__ float sm[];
    float* As = sm;                // [64][128] pf2 tile ; phase-2 Ws alias
    float* Bs = As + 8192;         // [64][256] pf4 tile ; phase-1 Ws alias
    float* bias = Bs + 16384;      // 256 (b4)
    int* idxs = (int*)(bias + 256);
    int tid = threadIdx.x;
    long long rb = (long long)blockIdx.x * 64;

    for (int i = tid * 4; i < 8192; i += 1024) {
        size_t flat = (size_t)rb * 128 + i;          // multiple of 4
        if (flat < (size_t)NPTS * 128)
            *(float4*)&As[i] = *(const float4*)&g_pf2[flat];
        else
            *(float4*)&As[i] = make_float4(0.f, 0.f, 0.f, 0.f);
    }
    if (tid < 64) {
        long long row = rb + tid;
        idxs[tid] = (row < NPTS) ? load_idx(idxp, row, g_idx_is64) : 0;
    }
    bias[tid] = b4[tid];
    __syncthreads();

    int cx = (tid & 31) * 4;
    int r0 = (tid >> 5) * 8;

    // Phase 1: Bs = relu(As @ W3[128:256,:] + g3[idx]) ; Ws inside Bs
    {
        u64 acc2[8][4];
        #pragma unroll
        for (int i = 0; i < 8; i++)
            #pragma unroll
            for (int j = 0; j < 4; j++) acc2[i][j] = 0ull;

        gemm_dbuf(As, 128, W3 + 128 * 256, 128, Bs, r0, cx, tid, acc2);
        __syncthreads();   // all Ws reads done before Bs epilogue overwrite

        #pragma unroll
        for (int i = 0; i < 8; i++) {
            const float* g3r = g_g3 + (size_t)idxs[r0 + i] * 256;
            #pragma unroll
            for (int j2 = 0; j2 < 4; j2++) {
                float lo, hi;
                unpack2(lo, hi, acc2[i][j2]);
                int c0 = col_of2(cx, j2, 0);
                Bs[(r0 + i) * 256 + c0]     = fmaxf(lo + g3r[c0], 0.f);
                Bs[(r0 + i) * 256 + c0 + 1] = fmaxf(hi + g3r[c0 + 1], 0.f);
            }
        }
    }
    __syncthreads();

    // Phase 2: pf5 = relu(Bs @ W4 + b4) ; Ws aliases As (dead) ; scatter-max
    {
        u64 acc2[8][4];
        #pragma unroll
        for (int i = 0; i < 8; i++)
            #pragma unroll
            for (int j = 0; j < 4; j++) acc2[i][j] = 0ull;

        gemm_dbuf(Bs, 256, W4, 256, As, r0, cx, tid, acc2);

        #pragma unroll
        for (int i = 0; i < 8; i++) {
            long long row = rb + r0 + i;
            if (row >= NPTS) continue;
            float* vr = g_vox2 + (size_t)idxs[r0 + i] * 256;
            #pragma unroll
            for (int j2 = 0; j2 < 4; j2++) {
                float lo, hi;
                unpack2(lo, hi, acc2[i][j2]);
                int c0 = col_of2(cx, j2, 0);
                float v0 = fmaxf(lo + bias[c0], 0.f);
                float v1 = fmaxf(hi + bias[c0 + 1], 0.f);
                if (v0 > vr[c0])
                    atomicMax((int*)&vr[c0], __float_as_int(v0));
                if (v1 > vr[c0 + 1])
                    atomicMax((int*)&vr[c0 + 1], __float_as_int(v1));
            }
        }
    }
}

// ---------------- K4: out = relu(vox2 @ Wv2 + bv2) --------------------------
// smem floats: As 16384 | Ws 8192 | bias 256
#define K4_SMEM_FLOATS (16384 + 8192 + 256)

__global__ void __launch_bounds__(256, 2)
k4(const float* __restrict__ Wv2, const float* __restrict__ bv2,
   float* __restrict__ out) {
    extern __shared__ float sm[];
    float* As = sm;               // [64][256]
    float* Ws = As + 16384;       // 2*[16][256]
    float* bias = Ws + 8192;      // 256
    int tid = threadIdx.x;
    int vb = blockIdx.x * 64;

    for (int i = tid * 4; i < 16384; i += 1024)
        *(float4*)&As[i] = *(const float4*)&g_vox2[(size_t)vb * 256 + i];
    bias[tid] = bv2[tid];
    __syncthreads();

    int cx = (tid & 31) * 4;
    int r0 = (tid >> 5) * 8;
    u64 acc2[8][4];
    #pragma unroll
    for (int i = 0; i < 8; i++)
        #pragma unroll
        for (int j = 0; j < 4; j++) acc2[i][j] = 0ull;

    gemm_dbuf(As, 256, Wv2, 256, Ws, r0, cx, tid, acc2);

    #pragma unroll
    for (int i = 0; i < 8; i++) {
        float* o = out + (size_t)(vb + r0 + i) * 256;
        #pragma unroll
        for (int j2 = 0; j2 < 4; j2++) {
            float lo, hi;
            unpack2(lo, hi, acc2[i][j2]);
            int c0 = col_of2(cx, j2, 0);
            o[c0]     = fmaxf(lo + bias[c0], 0.f);
            o[c0 + 1] = fmaxf(hi + bias[c0 + 1], 0.f);
        }
    }
}

// ---------------- launch ----------------------------------------------------
extern "C" void kernel_launch(void* const* d_in, const int* in_sizes, int n_in,
                              void* d_out, int out_size) {
    const float* inp  = (const float*)d_in[0];
    const void*  idxp = d_in[1];
    const float* W1   = (const float*)d_in[2];
    const float* b1   = (const float*)d_in[3];
    const float* W2   = (const float*)d_in[4];
    const float* b2   = (const float*)d_in[5];
    const float* Wv1  = (const float*)d_in[6];
    const float* bv1  = (const float*)d_in[7];
    const float* W3   = (const float*)d_in[8];
    const float* b3   = (const float*)d_in[9];
    const float* W4   = (const float*)d_in[10];
    const float* b4   = (const float*)d_in[11];
    const float* Wv2  = (const float*)d_in[12];
    const float* bv2  = (const float*)d_in[13];

    size_t sm1 = K1_SMEM_FLOATS * 4;
    size_t sm2 = K2_SMEM_FLOATS * 4;
    size_t sm3 = K3_SMEM_BYTES;
    size_t sm4 = K4_SMEM_FLOATS * 4;
    cudaFuncSetAttribute(k1, cudaFuncAttributeMaxDynamicSharedMemorySize, (int)sm1);
    cudaFuncSetAttribute(k2, cudaFuncAttributeMaxDynamicSharedMemorySize, (int)sm2);
    cudaFuncSetAttribute(k3, cudaFuncAttributeMaxDynamicSharedMemorySize, (int)sm3);
    cudaFuncSetAttribute(k4, cudaFuncAttributeMaxDynamicSharedMemorySize, (int)sm4);

    void *p1, *p2;
    cudaGetSymbolAddress(&p1, g_vox1);
    cudaGetSymbolAddress(&p2, g_vox2);
    cudaMemsetAsync(p1, 0, (size_t)NVOX * 128 * 4);
    cudaMemsetAsync(p2, 0, (size_t)NVOX * 256 * 4);

    kdetect<<<1, 256>>>((const unsigned*)idxp);
    k1<<<(NPTS + 255) / 256, 256, sm1>>>(inp, idxp, W1, b1, W2, b2);
    k2<<<NVOX / 64, 256, sm2>>>(Wv1, bv1, W3, b3);
    k3<<<(NPTS + 63) / 64, 256, sm3>>>(idxp, W3, W4, b4);
    k4<<<NVOX / 64, 256, sm4>>>(Wv2, bv2, (float*)d_out);
}